// round 1
// baseline (speedup 1.0000x reference)
#include <cuda_runtime.h>
#include <stdint.h>

// Row layout: segments (u,v) = (128,1),(64,3),(32,5),(16,7)
// offsets: 0, 128, 320, 480 ; total = 592
// out[off + a*u + b] = in[off + b*v + a],  a in [0,v), b in [0,u)
// => for output column c in segment: a = (c-off) >> log2(u), b = (c-off) & (u-1)
//    src = off + b*v + a

#define ROW_DIM 592
#define ROWS_PER_BLOCK 8
#define BLOCK_THREADS 256
#define FLOATS_PER_BLOCK (ROW_DIM * ROWS_PER_BLOCK)   // 4736
#define VEC4_PER_BLOCK (FLOATS_PER_BLOCK / 4)         // 1184

__device__ __forceinline__ int perm_src(int c) {
    // returns source column index within the row for output column c
    if (c < 128) {
        return c;                       // (128,1): identity
    } else if (c < 320) {
        int l = c - 128;                // (64,3)
        int a = l >> 6;                 // 0..2
        int b = l & 63;
        return 128 + b * 3 + a;
    } else if (c < 480) {
        int l = c - 320;                // (32,5)
        int a = l >> 5;                 // 0..4
        int b = l & 31;
        return 320 + b * 5 + a;
    } else {
        int l = c - 480;                // (16,7)
        int a = l >> 4;                 // 0..6
        int b = l & 15;
        return 480 + b * 7 + a;
    }
}

__global__ __launch_bounds__(BLOCK_THREADS, 4)
void transpose_irreps_kernel(const float* __restrict__ in, float* __restrict__ out, int n_rows) {
    __shared__ float smem[FLOATS_PER_BLOCK];

    const int tid = threadIdx.x;
    const long long block_elem_base = (long long)blockIdx.x * FLOATS_PER_BLOCK;

    // Phase 1: coalesced vectorized load of 8 rows into smem
    const float4* __restrict__ in4 = reinterpret_cast<const float4*>(in + block_elem_base);
    float4* __restrict__ sm4 = reinterpret_cast<float4*>(smem);
    #pragma unroll
    for (int i = tid; i < VEC4_PER_BLOCK; i += BLOCK_THREADS) {
        sm4[i] = in4[i];
    }
    __syncthreads();

    // Phase 2: coalesced stores; conflict-free smem gather (odd strides)
    float* __restrict__ out_base = out + block_elem_base;
    #pragma unroll
    for (int cb = 0; cb < ROW_DIM; cb += BLOCK_THREADS) {
        int c = cb + tid;
        if (c < ROW_DIM) {
            int s = perm_src(c);
            #pragma unroll
            for (int r = 0; r < ROWS_PER_BLOCK; r++) {
                out_base[r * ROW_DIM + c] = smem[r * ROW_DIM + s];
            }
        }
    }
}

extern "C" void kernel_launch(void* const* d_in, const int* in_sizes, int n_in,
                              void* d_out, int out_size) {
    const float* x = (const float*)d_in[0];
    float* out = (float*)d_out;
    int n_rows = in_sizes[0] / ROW_DIM;          // 200000
    int grid = n_rows / ROWS_PER_BLOCK;          // 25000 (exact: 200000 % 8 == 0)
    transpose_irreps_kernel<<<grid, BLOCK_THREADS>>>(x, out, n_rows);
}